// round 5
// baseline (speedup 1.0000x reference)
#include <cuda_runtime.h>
#include <math_constants.h>

// Problem constants (from reference setup_inputs)
static constexpr int NB  = 16;   // batch
static constexpr int CIN = 32;   // input channels
static constexpr int DIN = 16;
static constexpr int HIN = 32;
static constexpr int WIN = 32;
static constexpr int ODp = 5;    // pooled output dims
static constexpr int OHp = 10;
static constexpr int OWp = 10;

// Smem x tile: [c=32][ld=5][lh=5][lw padded to 33]
static constexpr int LWP      = 33;
static constexpr int XS_ELEMS = CIN * 5 * 5 * LWP;   // 26400
static constexpr int WS_ELEMS = 4000;                // 32 * 125
static constexpr int PM_ELEMS = 360;
static constexpr int SMEM_BYTES = (XS_ELEMS + WS_ELEMS + PM_ELEMS) * 4;  // 123,040 B

// Scratch: wsum[c*125+k] for c<32, k<125; [4000] = bias_sum
__device__ float g_wsum[4096];

// ---------------------------------------------------------------------------
// Kernel 1: wsum[c][k] = sum_o weight[c][o][k];  bias_sum = sum(bias)
// weight layout: (32, 64, 5,5,5) -> c*8000 + o*125 + k
// ---------------------------------------------------------------------------
__global__ void prep_kernel(const float* __restrict__ weight,
                            const float* __restrict__ bias) {
    int idx = blockIdx.x * blockDim.x + threadIdx.x;
    if (idx < 4000) {
        int c = idx / 125;
        int k = idx - c * 125;
        const float* p = weight + c * 8000 + k;
        float s = 0.f;
        #pragma unroll 8
        for (int o = 0; o < 64; o++) s += p[o * 125];
        g_wsum[idx] = s;
    } else if (idx == 4000) {
        float s = 0.f;
        #pragma unroll
        for (int o = 0; o < 64; o++) s += bias[o];
        g_wsum[4000] = s;
    }
}

// ---------------------------------------------------------------------------
// Kernel 2: fused transposed-conv (channel-summed) + 6x6x6/6 max pool.
//
// y[n, od, oh, ow] = sum_c sum_{kd,kh,kw with (o+2-k) even, in range}
//                      x[n, c, (od+2-kd)/2, (oh+2-kh)/2, (ow+2-kw)/2] * wsum[c,kd,kh,kw]
// out[n,d,h,w] = max over od in [6d,6d+6), oh in [6h,6h+6), ow in [6w,6w+6) of y  + bias_sum
//
// Block = (n, d, h): needs x[n, :, 3d-1..3d+3, 3h-1..3h+3, -1..30] (zero padded)
// Thread = one (od_l, oh_l, w-cell) strip of 6 ow points, parity-major ordering
// so warps share weight rows (LDS broadcast).
// ---------------------------------------------------------------------------
__global__ __launch_bounds__(360, 1)
void fused_kernel(const float* __restrict__ x, float* __restrict__ out) {
    extern __shared__ float smem[];
    float* XS = smem;                 // [32][5][5][LWP]
    float* WS = smem + XS_ELEMS;      // [32][125]
    float* PM = WS + WS_ELEMS;        // [360]

    const int h = blockIdx.x;
    const int d = blockIdx.y;
    const int n = blockIdx.z;
    const int tid = threadIdx.x;

    // Stage wsum (hits L2 after first block)
    for (int i = tid; i < WS_ELEMS; i += 360) WS[i] = g_wsum[i];

    // Stage x tile with zero padding. lw index = iw + 1, iw in [-1, 30].
    const int id0 = 3 * d - 1;
    const int ih0 = 3 * h - 1;
    const float* xn = x + (long)n * (CIN * DIN * HIN * WIN);
    for (int i = tid; i < CIN * 5 * 5 * 32; i += 360) {
        int lw = i & 31;
        int r  = i >> 5;
        int lh = r % 5; r /= 5;
        int ld = r % 5;
        int c  = r / 5;
        int id = id0 + ld, ih = ih0 + lh, iw = lw - 1;
        float v = 0.f;
        if ((unsigned)id < (unsigned)DIN && (unsigned)ih < (unsigned)HIN &&
            (unsigned)iw < (unsigned)WIN)
            v = xn[((c * DIN + id) * HIN + ih) * WIN + iw];
        XS[((c * 5 + ld) * 5 + lh) * LWP + lw] = v;
    }
    __syncthreads();

    // Parity-major thread mapping:
    //   cls = (pa<<1)|pb selects the (kd,kh) parity class (uniform tap counts),
    //   then a_off (od_l>>1), b_off (oh_l>>1), w.
    const int cls   = tid / 90;          // 0..3
    const int rem   = tid - cls * 90;
    const int pa    = cls >> 1;
    const int pb    = cls & 1;
    const int a_off = rem / 30;          // 0..2
    const int b_off = (rem / 10) % 3;    // 0..2
    const int w     = rem % 10;          // 0..9
    const int ns    = 3 - pa;            // # kd taps
    const int nt    = 3 - pb;            // # kh taps

    // od_l = 2*a_off + pa, oh_l = 2*b_off + pb. For tap s: ld = a_off+2-s,
    // kd = pa+2s. Same for (t, lh, kh). Along ow (strip of 6 at cell w):
    // ow_l = 2*half + pc, tap u: lw = 3w + half + 2 - u, kw = pc + 2u.
    float a0 = 0.f, a1 = 0.f, a2 = 0.f, a3 = 0.f, a4 = 0.f, a5 = 0.f;

    const int xrow_base = ((a_off + 2) * 5 + (b_off + 2)) * LWP + 3 * w;

    for (int c = 0; c < CIN; c++) {
        const float* XC = XS + c * (25 * LWP) + xrow_base;
        const float* WC = WS + c * 125;
        #pragma unroll
        for (int s = 0; s < 3; s++) {
            if (s >= ns) break;
            const int kd5 = (pa + 2 * s) * 5;
            #pragma unroll
            for (int t = 0; t < 3; t++) {
                if (t >= nt) break;
                const float* Xr = XC - (s * 5 + t) * LWP;
                const float* Wr = WC + (kd5 + (pb + 2 * t)) * 5;
                const float X0 = Xr[0], X1 = Xr[1], X2 = Xr[2], X3 = Xr[3], X4 = Xr[4];
                const float W0 = Wr[0], W1 = Wr[1], W2 = Wr[2], W3 = Wr[3], W4 = Wr[4];
                // ow_l = 0..5
                a0 = fmaf(X2, W0, fmaf(X1, W2, fmaf(X0, W4, a0)));
                a1 = fmaf(X2, W1, fmaf(X1, W3, a1));
                a2 = fmaf(X3, W0, fmaf(X2, W2, fmaf(X1, W4, a2)));
                a3 = fmaf(X3, W1, fmaf(X2, W3, a3));
                a4 = fmaf(X4, W0, fmaf(X3, W2, fmaf(X2, W4, a4)));
                a5 = fmaf(X4, W1, fmaf(X3, W3, a5));
            }
        }
    }

    // Max over this thread's 6 ow points
    float m = fmaxf(fmaxf(fmaxf(a0, a1), fmaxf(a2, a3)), fmaxf(a4, a5));
    PM[tid] = m;
    __syncthreads();

    // Reduce the 36 (od_l, oh_l) partials per w-cell and emit output
    if (tid < OWp) {
        float mm = -CUDART_INF_F;
        #pragma unroll
        for (int c2 = 0; c2 < 4; c2++)
            #pragma unroll
            for (int ab = 0; ab < 9; ab++)
                mm = fmaxf(mm, PM[c2 * 90 + ab * 10 + tid]);
        const float bs = g_wsum[4000];
        out[(((long)n * ODp + d) * OHp + h) * OWp + tid] = mm + bs;
    }
}

// ---------------------------------------------------------------------------
extern "C" void kernel_launch(void* const* d_in, const int* in_sizes, int n_in,
                              void* d_out, int out_size) {
    (void)in_sizes; (void)n_in; (void)out_size;
    const float* x      = (const float*)d_in[0];
    const float* weight = (const float*)d_in[1];
    const float* bias   = (const float*)d_in[2];
    float* out = (float*)d_out;

    // One-time opt-in to >48KB dynamic smem (host-side attribute; done before
    // graph capture since the first correctness call precedes capture).
    static bool s_attr_done = false;
    if (!s_attr_done) {
        cudaFuncSetAttribute(fused_kernel,
                             cudaFuncAttributeMaxDynamicSharedMemorySize,
                             SMEM_BYTES);
        s_attr_done = true;
    }

    prep_kernel<<<16, 256>>>(weight, bias);
    fused_kernel<<<dim3(OHp, ODp, NB), 360, SMEM_BYTES>>>(x, out);
}

// round 6
// speedup vs baseline: 1.4187x; 1.4187x over previous
#include <cuda_runtime.h>
#include <math_constants.h>

// Problem constants (from reference setup_inputs)
static constexpr int NB  = 16;   // batch
static constexpr int CIN = 32;   // input channels
static constexpr int DIN = 16;
static constexpr int HIN = 32;
static constexpr int WIN = 32;
static constexpr int ODp = 5;    // pooled output dims
static constexpr int OHp = 10;
static constexpr int OWp = 10;

// Channel chunking: 2 phases of 16 channels; accumulators persist in regs.
static constexpr int CHUNK = 16;
static constexpr int LWP   = 33;                      // padded x row (bank-conflict-free)
static constexpr int XS_ELEMS  = CHUNK * 5 * 5 * LWP; // 13200
static constexpr int WSP_ELEMS = CHUNK * 25 * 8;      // 3200 (rows padded 5->8 for v4 loads)
static constexpr int PM_ELEMS  = 360;
static constexpr int SMEM_BYTES = (XS_ELEMS + WSP_ELEMS + PM_ELEMS) * 4;  // 67,040 B

// wsum padded: [c][kd*5+kh][8] (5 kw + 3 pad); [6400] = bias_sum
__device__ float g_wsum_pad[6404];

// ---------------------------------------------------------------------------
// Kernel 1: wsum[c][row][kw] = sum_o weight[c][o][kd,kh,kw];  bias_sum
// weight layout: (32, 64, 5,5,5) -> c*8000 + o*125 + k
// ---------------------------------------------------------------------------
__global__ void prep_kernel(const float* __restrict__ weight,
                            const float* __restrict__ bias) {
    int idx = blockIdx.x * blockDim.x + threadIdx.x;
    if (idx < 4000) {
        int c = idx / 125;
        int k = idx - c * 125;
        const float* p = weight + c * 8000 + k;
        float s = 0.f;
        #pragma unroll 8
        for (int o = 0; o < 64; o++) s += p[o * 125];
        int row = k / 5, kw = k - row * 5;
        g_wsum_pad[c * 200 + row * 8 + kw] = s;
    } else if (idx == 4000) {
        float s = 0.f;
        #pragma unroll
        for (int o = 0; o < 64; o++) s += bias[o];
        g_wsum_pad[6400] = s;
    }
}

// ---------------------------------------------------------------------------
// Kernel 2: fused transposed-conv (channel-summed) + 6x6x6/6 max pool.
// Block = (n, d, h); thread = (parity-class, a_off, b_off, w-cell) -> 6 ow pts.
// Channels processed in 2 smem-resident chunks of 16 to allow 3 CTAs/SM.
// ---------------------------------------------------------------------------
__global__ __launch_bounds__(360, 3)
void fused_kernel(const float* __restrict__ x, float* __restrict__ out) {
    extern __shared__ float smem[];
    float* XS = smem;                  // [16][5][5][LWP]
    float* WS = smem + XS_ELEMS;       // [16][25][8]
    float* PM = WS + WSP_ELEMS;        // [360]

    const int h = blockIdx.x;
    const int d = blockIdx.y;
    const int n = blockIdx.z;
    const int tid = threadIdx.x;

    const int id0 = 3 * d - 1;
    const int ih0 = 3 * h - 1;
    const float* xn = x + (long)n * (CIN * DIN * HIN * WIN);

    // Parity-major thread mapping (same as proven-correct R4 kernel):
    const int cls   = tid / 90;          // (pa<<1)|pb
    const int rem   = tid - cls * 90;
    const int pa    = cls >> 1;
    const int pb    = cls & 1;
    const int a_off = rem / 30;          // 0..2
    const int b_off = (rem / 10) % 3;    // 0..2
    const int w     = rem % 10;          // 0..9
    const int ns    = 3 - pa;            // # kd taps
    const int nt    = 3 - pb;            // # kh taps

    float a0 = 0.f, a1 = 0.f, a2 = 0.f, a3 = 0.f, a4 = 0.f, a5 = 0.f;
    const int xrow_base = ((a_off + 2) * 5 + (b_off + 2)) * LWP + 3 * w;

    #pragma unroll
    for (int chunk = 0; chunk < 2; chunk++) {
        // ---- stage x chunk (16 channels) with zero padding ----
        for (int i = tid; i < CHUNK * 5 * 5 * 32; i += 360) {
            int lw = i & 31;
            int r  = i >> 5;
            int lh = r % 5; r /= 5;
            int ld = r % 5;
            int c  = r / 5;                       // 0..15 local
            int id = id0 + ld, ih = ih0 + lh, iw = lw - 1;
            float v = 0.f;
            if ((unsigned)id < (unsigned)DIN && (unsigned)ih < (unsigned)HIN &&
                (unsigned)iw < (unsigned)WIN)
                v = xn[(((chunk * CHUNK + c) * DIN + id) * HIN + ih) * WIN + iw];
            XS[((c * 5 + ld) * 5 + lh) * LWP + lw] = v;
        }
        // ---- stage padded wsum chunk ----
        for (int i = tid; i < WSP_ELEMS; i += 360)
            WS[i] = g_wsum_pad[chunk * WSP_ELEMS + i];
        __syncthreads();

        // ---- accumulate over this chunk's 16 channels ----
        for (int c = 0; c < CHUNK; c++) {
            const float* XC = XS + c * (25 * LWP) + xrow_base;
            const float* WC = WS + c * 200;
            #pragma unroll
            for (int s = 0; s < 3; s++) {
                if (s >= ns) break;
                const int kd5 = (pa + 2 * s) * 5;
                #pragma unroll
                for (int t = 0; t < 3; t++) {
                    if (t >= nt) break;
                    const float* Xr = XC - (s * 5 + t) * LWP;
                    const float* Wr = WC + (kd5 + (pb + 2 * t)) * 8;
                    const float X0 = Xr[0], X1 = Xr[1], X2 = Xr[2], X3 = Xr[3], X4 = Xr[4];
                    const float4 wv = *reinterpret_cast<const float4*>(Wr);
                    const float W0 = wv.x, W1 = wv.y, W2 = wv.z, W3 = wv.w;
                    const float W4 = Wr[4];
                    // ow_l = 0..5 of this w-cell
                    a0 = fmaf(X2, W0, fmaf(X1, W2, fmaf(X0, W4, a0)));
                    a1 = fmaf(X2, W1, fmaf(X1, W3, a1));
                    a2 = fmaf(X3, W0, fmaf(X2, W2, fmaf(X1, W4, a2)));
                    a3 = fmaf(X3, W1, fmaf(X2, W3, a3));
                    a4 = fmaf(X4, W0, fmaf(X3, W2, fmaf(X2, W4, a4)));
                    a5 = fmaf(X4, W1, fmaf(X3, W3, a5));
                }
            }
        }
        __syncthreads();   // protect XS/WS before next chunk's staging
    }

    // Max over this thread's 6 ow points
    float m = fmaxf(fmaxf(fmaxf(a0, a1), fmaxf(a2, a3)), fmaxf(a4, a5));
    PM[tid] = m;
    __syncthreads();

    // Reduce the 36 (od_l, oh_l) partials per w-cell and emit output
    if (tid < OWp) {
        float mm = -CUDART_INF_F;
        #pragma unroll
        for (int c2 = 0; c2 < 4; c2++)
            #pragma unroll
            for (int ab = 0; ab < 9; ab++)
                mm = fmaxf(mm, PM[c2 * 90 + ab * 10 + tid]);
        const float bs = g_wsum_pad[6400];
        out[(((long)n * ODp + d) * OHp + h) * OWp + tid] = mm + bs;
    }
}

// ---------------------------------------------------------------------------
extern "C" void kernel_launch(void* const* d_in, const int* in_sizes, int n_in,
                              void* d_out, int out_size) {
    (void)in_sizes; (void)n_in; (void)out_size;
    const float* x      = (const float*)d_in[0];
    const float* weight = (const float*)d_in[1];
    const float* bias   = (const float*)d_in[2];
    float* out = (float*)d_out;

    static bool s_attr_done = false;
    if (!s_attr_done) {
        cudaFuncSetAttribute(fused_kernel,
                             cudaFuncAttributeMaxDynamicSharedMemorySize,
                             SMEM_BYTES);
        s_attr_done = true;
    }

    prep_kernel<<<16, 256>>>(weight, bias);
    fused_kernel<<<dim3(OHp, ODp, NB), 360, SMEM_BYTES>>>(x, out);
}

// round 7
// speedup vs baseline: 1.6559x; 1.1672x over previous
#include <cuda_runtime.h>
#include <math_constants.h>

// Problem constants (from reference setup_inputs)
static constexpr int NB  = 16;   // batch
static constexpr int CIN = 32;   // input channels
static constexpr int DIN = 16;
static constexpr int HIN = 32;
static constexpr int WIN = 32;
static constexpr int ODp = 5;    // pooled output dims
static constexpr int OHp = 10;
static constexpr int OWp = 10;

// Channel chunking: 4 phases of 8 channels; 18 accumulators persist in regs.
static constexpr int CHUNK = 8;
static constexpr int LWP   = 33;                       // padded x row (conflict-free)
static constexpr int XS_ELEMS  = CHUNK * 5 * 5 * LWP;  // 6600
static constexpr int WSP_ELEMS = CHUNK * 25 * 8;       // 1600 (rows padded 5->8)
static constexpr int PM_ELEMS  = 128;
static constexpr int SMEM_BYTES = (XS_ELEMS + WSP_ELEMS + PM_ELEMS) * 4;  // 33,312 B

// wsum padded: [c][kd*5+kh][8] (5 kw + 3 pad); [6400] = bias_sum
__device__ float g_wsum_pad[6404];

// ---------------------------------------------------------------------------
// Kernel 1: wsum[c][row][kw] = sum_o weight[c][o][kd,kh,kw];  bias_sum
// weight layout: (32, 64, 5,5,5) -> c*8000 + o*125 + k
// ---------------------------------------------------------------------------
__global__ void prep_kernel(const float* __restrict__ weight,
                            const float* __restrict__ bias) {
    int idx = blockIdx.x * blockDim.x + threadIdx.x;
    if (idx < 4000) {
        int c = idx / 125;
        int k = idx - c * 125;
        const float* p = weight + c * 8000 + k;
        float s = 0.f;
        #pragma unroll 8
        for (int o = 0; o < 64; o++) s += p[o * 125];
        int row = k / 5, kw = k - row * 5;
        g_wsum_pad[c * 200 + row * 8 + kw] = s;
    } else if (idx == 4000) {
        float s = 0.f;
        #pragma unroll
        for (int o = 0; o < 64; o++) s += bias[o];
        g_wsum_pad[6400] = s;
    }
}

// ---------------------------------------------------------------------------
// Per-chunk compute, specialized per parity class (PA = od parity, PB = oh
// parity). Thread owns all 3 a_off values (od_l = 2*a_off + PA) for its
// (b_off, w) cell: 18 accumulators acc[a_off*6 + ow_l].
// Identity: od_l = 2*ld + kd - 4, kd = PA + 2s  =>  a_off = ld - 2 + s.
// ---------------------------------------------------------------------------
template <int PA, int PB>
__device__ __forceinline__ void compute_chunk(const float* __restrict__ XS,
                                              const float* __restrict__ WS,
                                              int b_off, int w,
                                              float (&acc)[18]) {
    constexpr int NS = 3 - PA;   // # kd taps
    constexpr int NT = 3 - PB;   // # kh taps
    const int xcol = 3 * w;

    for (int c = 0; c < CHUNK; c++) {
        const float* XC = XS + c * (25 * LWP);
        const float* WC = WS + c * 200;
        #pragma unroll
        for (int t = 0; t < NT; t++) {
            const int lh = b_off + 2 - t;
            const int kh = PB + 2 * t;
            // Hoist the NS weight rows for this (kh) column (warp-broadcast).
            float4 wv[NS];
            float  w4[NS];
            #pragma unroll
            for (int s = 0; s < NS; s++) {
                const float* Wr = WC + ((PA + 2 * s) * 5 + kh) * 8;
                wv[s] = *reinterpret_cast<const float4*>(Wr);
                w4[s] = Wr[4];
            }
            #pragma unroll
            for (int ld = 0; ld < 5; ld++) {
                // s range with 0 <= a_off = ld-2+s <= 2 and s < NS
                constexpr int dummy = 0; (void)dummy;
                const int s_lo = (2 - ld) > 0 ? (2 - ld) : 0;
                const int s_hi_a = 4 - ld;
                const int s_hi = s_hi_a < (NS - 1) ? s_hi_a : (NS - 1);
                if (s_lo > s_hi) continue;   // folds at compile time (unrolled)

                const float* Xr = XC + (ld * 5 + lh) * LWP + xcol;
                const float X0 = Xr[0], X1 = Xr[1], X2 = Xr[2],
                            X3 = Xr[3], X4 = Xr[4];
                #pragma unroll
                for (int s = 0; s < NS; s++) {
                    if (s < s_lo || s > s_hi) continue;
                    const int ao = ld - 2 + s;
                    float* a = acc + ao * 6;
                    const float W0 = wv[s].x, W1 = wv[s].y, W2 = wv[s].z,
                                W3 = wv[s].w, W4 = w4[s];
                    a[0] = fmaf(X2, W0, fmaf(X1, W2, fmaf(X0, W4, a[0])));
                    a[1] = fmaf(X2, W1, fmaf(X1, W3, a[1]));
                    a[2] = fmaf(X3, W0, fmaf(X2, W2, fmaf(X1, W4, a[2])));
                    a[3] = fmaf(X3, W1, fmaf(X2, W3, a[3]));
                    a[4] = fmaf(X4, W0, fmaf(X3, W2, fmaf(X2, W4, a[4])));
                    a[5] = fmaf(X4, W1, fmaf(X3, W3, a[5]));
                }
            }
        }
    }
}

// ---------------------------------------------------------------------------
// Kernel 2: fused transposed-conv (channel-summed) + 6x6x6/6 max pool.
// Block = (n, d, h); 128 threads = 4 class-uniform warps; lanes 0..29 own
// (b_off, w); each thread computes 18 y-points (3 od x 6 ow).
// ---------------------------------------------------------------------------
__global__ __launch_bounds__(128, 6)
void fused_kernel(const float* __restrict__ x, float* __restrict__ out) {
    extern __shared__ float smem[];
    float* XS = smem;                  // [8][5][5][LWP]
    float* WS = smem + XS_ELEMS;       // [8][25][8]
    float* PM = WS + WSP_ELEMS;        // [128]

    const int h = blockIdx.x;
    const int d = blockIdx.y;
    const int n = blockIdx.z;
    const int tid  = threadIdx.x;
    const int wp   = tid >> 5;         // parity class: (pa<<1)|pb
    const int lane = tid & 31;
    const bool active = lane < 30;
    const int b_off = lane / 10;       // 0..2 (garbage for lane>=30, unused)
    const int w     = lane - b_off * 10;

    const int id0 = 3 * d - 1;
    const int ih0 = 3 * h - 1;
    const float* xn = x + (long)n * (CIN * DIN * HIN * WIN);

    float acc[18];
    #pragma unroll
    for (int i = 0; i < 18; i++) acc[i] = 0.f;

    for (int chunk = 0; chunk < 4; chunk++) {
        // ---- stage x chunk (8 channels) with zero padding ----
        for (int i = tid; i < CHUNK * 5 * 5 * 32; i += 128) {
            int lw = i & 31;
            int r  = i >> 5;
            int lh = r % 5;
            int ld = (r / 5) % 5;
            int c  = r / 25;                    // 0..7 local
            int id = id0 + ld, ih = ih0 + lh, iw = lw - 1;
            float v = 0.f;
            if ((unsigned)id < (unsigned)DIN && (unsigned)ih < (unsigned)HIN &&
                (unsigned)iw < (unsigned)WIN)
                v = xn[(((chunk * CHUNK + c) * DIN + id) * HIN + ih) * WIN + iw];
            XS[((c * 5 + ld) * 5 + lh) * LWP + lw] = v;
        }
        // ---- stage padded wsum chunk ----
        for (int i = tid; i < WSP_ELEMS; i += 128)
            WS[i] = g_wsum_pad[chunk * WSP_ELEMS + i];
        __syncthreads();

        if (active) {
            if      (wp == 0) compute_chunk<0, 0>(XS, WS, b_off, w, acc);
            else if (wp == 1) compute_chunk<0, 1>(XS, WS, b_off, w, acc);
            else if (wp == 2) compute_chunk<1, 0>(XS, WS, b_off, w, acc);
            else              compute_chunk<1, 1>(XS, WS, b_off, w, acc);
        }
        __syncthreads();   // protect XS/WS before next chunk's staging
    }

    // Max over this thread's 18 y-points
    float m = -CUDART_INF_F;
    #pragma unroll
    for (int i = 0; i < 18; i++) m = fmaxf(m, acc[i]);
    PM[tid] = m;
    __syncthreads();

    // Reduce the 12 (class, b_off) partials per w-cell and emit output
    if (tid < OWp) {
        float mm = -CUDART_INF_F;
        #pragma unroll
        for (int c2 = 0; c2 < 4; c2++)
            #pragma unroll
            for (int bo = 0; bo < 3; bo++)
                mm = fmaxf(mm, PM[c2 * 32 + bo * 10 + tid]);
        const float bs = g_wsum_pad[6400];
        out[(((long)n * ODp + d) * OHp + h) * OWp + tid] = mm + bs;
    }
}

// ---------------------------------------------------------------------------
extern "C" void kernel_launch(void* const* d_in, const int* in_sizes, int n_in,
                              void* d_out, int out_size) {
    (void)in_sizes; (void)n_in; (void)out_size;
    const float* x      = (const float*)d_in[0];
    const float* weight = (const float*)d_in[1];
    const float* bias   = (const float*)d_in[2];
    float* out = (float*)d_out;

    prep_kernel<<<16, 256>>>(weight, bias);
    fused_kernel<<<dim3(OHp, ODp, NB), 128, SMEM_BYTES>>>(x, out);
}

// round 8
// speedup vs baseline: 2.0483x; 1.2370x over previous
#include <cuda_runtime.h>
#include <math_constants.h>

// Problem constants (from reference setup_inputs)
static constexpr int NB  = 16;   // batch
static constexpr int CIN = 32;   // input channels
static constexpr int DIN = 16;
static constexpr int HIN = 32;
static constexpr int WIN = 32;
static constexpr int ODp = 5;    // pooled output dims
static constexpr int OHp = 10;
static constexpr int OWp = 10;

// Channel chunking: 4 phases of 8 channels; 9 packed accumulators in regs.
static constexpr int CHUNK = 8;
static constexpr int LWP   = 33;                       // padded x row (conflict-free)
static constexpr int XS_ELEMS  = CHUNK * 5 * 5 * LWP;  // 6600
static constexpr int PM_ELEMS  = 128;
static constexpr int SMEM_BYTES = (XS_ELEMS + PM_ELEMS) * 4;  // 26,912 B

// wsum padded: [c][kd*5+kh][8] (5 kw + 3 ZERO pads -> {W4,0} 64-bit loads);
// [6400] = bias_sum
__device__ float g_wsum_pad[6404];

typedef unsigned long long ull;

#define FMA2(d, a, b) \
    asm("fma.rn.f32x2 %0, %1, %2, %0;" : "+l"(d) : "l"(a), "l"(b))

__device__ __forceinline__ ull bcast2(float x) {
    ull r;
    asm("mov.b64 %0, {%1, %1};" : "=l"(r) : "f"(x));
    return r;
}
__device__ __forceinline__ float2 unpack2(ull v) {
    float lo, hi;
    asm("mov.b64 {%0, %1}, %2;" : "=f"(lo), "=f"(hi) : "l"(v));
    return make_float2(lo, hi);
}

// ---------------------------------------------------------------------------
// Kernel 1: wsum[c][row][kw] = sum_o weight[c][o][kd,kh,kw] (pads = 0);
// bias_sum at [6400].  weight layout: (32,64,5,5,5) -> c*8000 + o*125 + k
// ---------------------------------------------------------------------------
__global__ void prep_kernel(const float* __restrict__ weight,
                            const float* __restrict__ bias) {
    int idx = blockIdx.x * blockDim.x + threadIdx.x;
    if (idx < 6400) {
        int c   = idx / 200;
        int rem = idx - c * 200;
        int row = rem >> 3;
        int col = rem & 7;
        float s = 0.f;
        if (col < 5) {
            const float* p = weight + c * 8000 + row * 5 + col;
            #pragma unroll 8
            for (int o = 0; o < 64; o++) s += p[o * 125];
        }
        g_wsum_pad[idx] = s;   // pads (col>=5) get 0
    } else if (idx == 6400) {
        float s = 0.f;
        #pragma unroll
        for (int o = 0; o < 64; o++) s += bias[o];
        g_wsum_pad[6400] = s;
    }
}

// ---------------------------------------------------------------------------
// Per-chunk compute, specialized per parity class (PA = od parity, PB = oh
// parity). Thread owns 3 a_off x 6 ow = 18 y-points as 9 f32x2 accumulators
// acc[ao*3 + p], p in {ow01, ow23, ow45}.
// Identity: od_l = 2*ld + kd - 4, kd = PA + 2s  =>  a_off = ld - 2 + s.
// Weights read as warp-uniform 64-bit __ldg broadcasts from g_wsum_pad.
// ---------------------------------------------------------------------------
template <int PA, int PB>
__device__ __forceinline__ void compute_chunk(const float* __restrict__ XS,
                                              const float* __restrict__ gw,
                                              int b_off, int w,
                                              ull (&acc)[9]) {
    constexpr int NS = 3 - PA;   // # kd taps
    constexpr int NT = 3 - PB;   // # kh taps
    const int xcol = 3 * w;

    for (int c = 0; c < CHUNK; c++) {
        const float* XC = XS + c * (25 * LWP);
        const float* WC = gw + c * 200;
        #pragma unroll
        for (int t = 0; t < NT; t++) {
            const int lh = b_off + 2 - t;
            const int kh = PB + 2 * t;
            // Hoist the NS weight rows as packed 64-bit broadcasts.
            ull W01[NS], W23[NS], W40[NS];
            #pragma unroll
            for (int s = 0; s < NS; s++) {
                const ull* wr = reinterpret_cast<const ull*>(
                    WC + ((PA + 2 * s) * 5 + kh) * 8);
                W01[s] = __ldg(wr);
                W23[s] = __ldg(wr + 1);
                W40[s] = __ldg(wr + 2);   // {W4, 0} thanks to zero padding
            }
            #pragma unroll
            for (int ld = 0; ld < 5; ld++) {
                const int s_lo = (2 - ld) > 0 ? (2 - ld) : 0;
                const int s_hi_a = 4 - ld;
                const int s_hi = s_hi_a < (NS - 1) ? s_hi_a : (NS - 1);
                if (s_lo > s_hi) continue;   // folds at compile time

                const float* Xr = XC + (ld * 5 + lh) * LWP + xcol;
                const ull XX0 = bcast2(Xr[0]);
                const ull XX1 = bcast2(Xr[1]);
                const ull XX2 = bcast2(Xr[2]);
                const ull XX3 = bcast2(Xr[3]);
                const ull XX4 = bcast2(Xr[4]);
                #pragma unroll
                for (int s = 0; s < NS; s++) {
                    if (s < s_lo || s > s_hi) continue;
                    const int ao = ld - 2 + s;
                    ull* P = acc + ao * 3;
                    FMA2(P[0], XX2, W01[s]);
                    FMA2(P[0], XX1, W23[s]);
                    FMA2(P[0], XX0, W40[s]);
                    FMA2(P[1], XX3, W01[s]);
                    FMA2(P[1], XX2, W23[s]);
                    FMA2(P[1], XX1, W40[s]);
                    FMA2(P[2], XX4, W01[s]);
                    FMA2(P[2], XX3, W23[s]);
                    FMA2(P[2], XX2, W40[s]);
                }
            }
        }
    }
}

// ---------------------------------------------------------------------------
// Kernel 2: fused transposed-conv (channel-summed) + 6x6x6/6 max pool.
// Block = (n, d, h); 128 threads = 4 class-uniform warps; lanes 0..29 own
// (b_off, w); each thread computes 18 y-points (3 od x 6 ow).
// ---------------------------------------------------------------------------
__global__ __launch_bounds__(128, 7)
void fused_kernel(const float* __restrict__ x, float* __restrict__ out) {
    extern __shared__ float smem[];
    float* XS = smem;                  // [8][5][5][LWP]
    float* PM = smem + XS_ELEMS;       // [128]

    const int h = blockIdx.x;
    const int d = blockIdx.y;
    const int n = blockIdx.z;
    const int tid   = threadIdx.x;
    const int wp    = tid >> 5;        // parity class: (pa<<1)|pb
    const int lane  = tid & 31;
    const int b_off = lane / 10;       // 0..2 (lanes 30,31 compute garbage, never stored)
    const int w     = lane - b_off * 10;

    const int id0 = 3 * d - 1;
    const int ih0 = 3 * h - 1;
    const float* xn = x + (long)n * (CIN * DIN * HIN * WIN);

    // --- precompute staging row tables (div/mod done once) ---
    const int rowid = tid >> 5;        // 0..3; rows r = rowid + 4*rr
    bool rok[7], vld[7];
    int  goff[7], doff[7];
    #pragma unroll
    for (int rr = 0; rr < 7; rr++) {
        int r  = rowid + 4 * rr;
        rok[rr] = (r < 25);
        int rc = r < 25 ? r : 24;
        int ld = rc / 5;
        int lh = rc - ld * 5;
        int id = id0 + ld;
        int ih = ih0 + lh;
        vld[rr]  = (id >= 0) && (ih >= 0);   // upper bounds always in range
        goff[rr] = id * (HIN * WIN) + ih * WIN + lane;
        doff[rr] = rc * LWP + 1 + lane;      // lw = iw + 1
    }

    ull acc[9];
    #pragma unroll
    for (int i = 0; i < 9; i++) acc[i] = 0ull;

    for (int chunk = 0; chunk < 4; chunk++) {
        if (chunk) __syncthreads();          // protect XS before re-staging
        // ---- stage x chunk (8 channels): lanes map 1:1 to iw, coalesced ----
        const float* xc = xn + chunk * (CHUNK * DIN * HIN * WIN);
        for (int c = 0; c < CHUNK; c++) {
            const int bg = c * (DIN * HIN * WIN);
            const int bd = c * (25 * LWP);
            #pragma unroll
            for (int rr = 0; rr < 7; rr++) {
                if (rok[rr]) {
                    float v = vld[rr] ? __ldg(xc + bg + goff[rr]) : 0.f;
                    XS[bd + doff[rr]] = v;
                    if (lane == 0) XS[bd + doff[rr] - 1] = 0.f;  // lw=0 pad col
                }
            }
        }
        __syncthreads();

        const float* gw = g_wsum_pad + chunk * (CHUNK * 200);
        if      (wp == 0) compute_chunk<0, 0>(XS, gw, b_off, w, acc);
        else if (wp == 1) compute_chunk<0, 1>(XS, gw, b_off, w, acc);
        else if (wp == 2) compute_chunk<1, 0>(XS, gw, b_off, w, acc);
        else              compute_chunk<1, 1>(XS, gw, b_off, w, acc);
    }

    // Max over this thread's 18 y-points
    float m = -CUDART_INF_F;
    #pragma unroll
    for (int i = 0; i < 9; i++) {
        float2 v = unpack2(acc[i]);
        m = fmaxf(m, fmaxf(v.x, v.y));
    }
    PM[tid] = m;
    __syncthreads();

    // Reduce the 12 (class, b_off) partials per w-cell and emit output
    if (tid < OWp) {
        float mm = -CUDART_INF_F;
        #pragma unroll
        for (int c2 = 0; c2 < 4; c2++)
            #pragma unroll
            for (int bo = 0; bo < 3; bo++)
                mm = fmaxf(mm, PM[c2 * 32 + bo * 10 + tid]);
        const float bs = g_wsum_pad[6400];
        out[(((long)n * ODp + d) * OHp + h) * OWp + tid] = mm + bs;
    }
}

// ---------------------------------------------------------------------------
extern "C" void kernel_launch(void* const* d_in, const int* in_sizes, int n_in,
                              void* d_out, int out_size) {
    (void)in_sizes; (void)n_in; (void)out_size;
    const float* x      = (const float*)d_in[0];
    const float* weight = (const float*)d_in[1];
    const float* bias   = (const float*)d_in[2];
    float* out = (float*)d_out;

    prep_kernel<<<26, 256>>>(weight, bias);
    fused_kernel<<<dim3(OHp, ODp, NB), 128, SMEM_BYTES>>>(x, out);
}